// round 11
// baseline (speedup 1.0000x reference)
#include <cuda_runtime.h>

#define BB      4096
#define DD      8192
#define KK      5
#define GS      40
#define CKLEN   17
#define CKPAD   20
#define NTHR    256
#define TILE    2048                    // outputs per block
#define TILES_PER_ROW (DD / TILE)       // 4

// batch-global max of |g|/GS, produced by maxit_kernel
__device__ int g_maxit;

// ---------------------------------------------------------------------------
// Kernel A: tiny reduction, 1 block. max_it = max_b |g[b]| / GS
// ---------------------------------------------------------------------------
__global__ void __launch_bounds__(NTHR)
maxit_kernel(const int* __restrict__ g)
{
    __shared__ int s[NTHR / 32];
    const int t = threadIdx.x;
    int m = 0;
    #pragma unroll
    for (int i = t; i < BB; i += NTHR) {
        int v = __ldg(g + i);
        int a = v < 0 ? -v : v;
        m = max(m, a / GS);
    }
    #pragma unroll
    for (int o = 16; o > 0; o >>= 1)
        m = max(m, __shfl_xor_sync(0xffffffffu, m, o));
    if ((t & 31) == 0) s[t >> 5] = m;
    __syncthreads();
    if (t == 0) {
        #pragma unroll
        for (int w = 1; w < NTHR / 32; w++) m = max(m, s[w]);
        g_maxit = m;
    }
}

// ---------------------------------------------------------------------------
// Kernel B: fused compose + 17-tap circular correlation.
//  - all 10 x-window LDG.128 issued first (no dependency on kernel A)
//  - griddepsync (PDL) -> warp 0 composes the row's taps warp-parallel
//    (lane p owns tap p; 4 shfl + 5 FMA per stage), writes smem
//  - syncthreads -> all threads read taps, 2 compute rounds, streaming stores
// ---------------------------------------------------------------------------
__global__ void __launch_bounds__(NTHR, 4)
conv_main(const float* __restrict__ x,
          const int*   __restrict__ g,
          const float* __restrict__ kernels,
          float*       __restrict__ out)
{
    __shared__ float s_k[CKPAD];

    const int bid  = blockIdx.x;
    const int b    = bid >> 2;              // TILES_PER_ROW = 4
    const int tile = bid & 3;
    const int lane = threadIdx.x & 31;
    const int warp = threadIdx.x >> 5;

    const float* __restrict__ xr = x + (size_t)b * DD;
    float* __restrict__ orow     = out + (size_t)b * DD;

    const int base4 = tile * (TILE / 4) + warp * 64 + lane;
    const int d0 = base4 * 4;
    const int d1 = d0 + 128;

    // ---- issue all 10 window loads up front (independent of kernel A) ----
    float w0[20], w1[20];
    #pragma unroll
    for (int q = 0; q < 5; q++) {
        const int idx = (d0 - 8 + 4 * q) & (DD - 1);
        float4 v = __ldg(reinterpret_cast<const float4*>(xr + idx));
        w0[4*q+0] = v.x; w0[4*q+1] = v.y; w0[4*q+2] = v.z; w0[4*q+3] = v.w;
    }
    #pragma unroll
    for (int q = 0; q < 5; q++) {
        const int idx = (d1 - 8 + 4 * q) & (DD - 1);
        float4 v = __ldg(reinterpret_cast<const float4*>(xr + idx));
        w1[4*q+0] = v.x; w1[4*q+1] = v.y; w1[4*q+2] = v.z; w1[4*q+3] = v.w;
    }

#if __CUDA_ARCH__ >= 900
    cudaGridDependencySynchronize();   // wait for maxit_kernel
#endif

    // ---- warp 0: compose this row's 17 taps (lane p = tap p) ----
    if (warp == 0) {
        const int gv  = __ldg(g + b);
        const int sgn = (gv > 0) - (gv < 0);
        const int av  = gv < 0 ? -gv : gv;
        const int it  = av / GS;
        const int rem = av - it * GS;
        const int max_it = g_maxit;

        float idk[KK], maxk[KK], fink[KK];
        const int midx = sgn * 40 + 40;
        const int fidx = rem * sgn + 40;
        #pragma unroll
        for (int j = 0; j < KK; j++) {
            idk[j]  = __ldg(kernels + 40   * KK + j);
            maxk[j] = __ldg(kernels + midx * KK + j);
            fink[j] = __ldg(kernels + fidx * KK + j);
        }

        // lanes 17..31 carry c = 0 throughout (support never reaches them)
        float c = (lane == 8) ? 1.f : 0.f;

        #pragma unroll
        for (int stage = 0; stage < 4; stage++) {
            float k0, k1, k2, k3, k4;
            bool skip = false;
            if (stage == 3) {
                k0=fink[0]; k1=fink[1]; k2=fink[2]; k3=fink[3]; k4=fink[4];
            } else if (stage < it) {
                k0=maxk[0]; k1=maxk[1]; k2=maxk[2]; k3=maxk[3]; k4=maxk[4];
            } else if (stage < max_it) {
                k0=idk[0];  k1=idk[1];  k2=idk[2];  k3=idk[3];  k4=idk[4];
            } else {
                skip = true;           // true delta -> identity
                k0=k1=k2=k3=k4=0.f;
            }
            if (!skip) {
                // new_c[p] = sum_j kk[j] * c[p - j + 2]
                float cd2 = __shfl_down_sync(0xffffffffu, c, 2);
                float cd1 = __shfl_down_sync(0xffffffffu, c, 1);
                float cu1 = __shfl_up_sync  (0xffffffffu, c, 1);
                float cu2 = __shfl_up_sync  (0xffffffffu, c, 2);
                // out-of-range shfl self-returns: multiplied values are 0
                // at every lane where it matters (support argument).
                float nc;
                nc = k0 * cd2;
                nc = fmaf(k1, cd1, nc);
                nc = fmaf(k2, c,   nc);
                nc = fmaf(k3, cu1, nc);
                nc = fmaf(k4, cu2, nc);
                c = nc;
            }
        }

        if (lane < CKPAD) s_k[lane] = (lane < CKLEN) ? c : 0.f;
    }
    __syncthreads();

    // ---- taps from smem (broadcast, conflict-free) ----
    float k[CKLEN];
    {
        const float4* sk = reinterpret_cast<const float4*>(s_k);
        float4 k0 = sk[0], k1 = sk[1], k2 = sk[2], k3 = sk[3], k4 = sk[4];
        k[0]=k0.x;  k[1]=k0.y;  k[2]=k0.z;  k[3]=k0.w;
        k[4]=k1.x;  k[5]=k1.y;  k[6]=k1.z;  k[7]=k1.w;
        k[8]=k2.x;  k[9]=k2.y;  k[10]=k2.z; k[11]=k2.w;
        k[12]=k3.x; k[13]=k3.y; k[14]=k3.z; k[15]=k3.w;
        k[16]=k4.x;
    }

    // ---- round 0 ----
    {
        float a0 = 0.f, a1 = 0.f, a2 = 0.f, a3 = 0.f;
        #pragma unroll
        for (int p = 0; p < CKLEN; p++) {
            a0 = fmaf(k[p], w0[p + 0], a0);
            a1 = fmaf(k[p], w0[p + 1], a1);
            a2 = fmaf(k[p], w0[p + 2], a2);
            a3 = fmaf(k[p], w0[p + 3], a3);
        }
        __stcs(reinterpret_cast<float4*>(orow + d0), make_float4(a0, a1, a2, a3));
    }

    // ---- round 1 ----
    {
        float a0 = 0.f, a1 = 0.f, a2 = 0.f, a3 = 0.f;
        #pragma unroll
        for (int p = 0; p < CKLEN; p++) {
            a0 = fmaf(k[p], w1[p + 0], a0);
            a1 = fmaf(k[p], w1[p + 1], a1);
            a2 = fmaf(k[p], w1[p + 2], a2);
            a3 = fmaf(k[p], w1[p + 3], a3);
        }
        __stcs(reinterpret_cast<float4*>(orow + d1), make_float4(a0, a1, a2, a3));
    }
}

// ---------------------------------------------------------------------------
// Launch: tiny max reduce, then fused conv with PDL so conv's load prologue
// overlaps the reduction.
// ---------------------------------------------------------------------------
extern "C" void kernel_launch(void* const* d_in, const int* in_sizes, int n_in,
                              void* d_out, int out_size)
{
    const float* x       = (const float*)d_in[0];   // [4096, 8192] f32
    const int*   g       = (const int*)  d_in[1];   // [4096] i32
    const float* kernels = (const float*)d_in[2];   // [81, 5] f32
    float*       out     = (float*)d_out;           // [4096, 1, 8192] f32

    maxit_kernel<<<1, NTHR>>>(g);

    cudaLaunchConfig_t cfg = {};
    cfg.gridDim  = dim3(BB * TILES_PER_ROW, 1, 1);
    cfg.blockDim = dim3(NTHR, 1, 1);
    cfg.dynamicSmemBytes = 0;
    cfg.stream = 0;
    cudaLaunchAttribute attrs[1];
    attrs[0].id = cudaLaunchAttributeProgrammaticStreamSerialization;
    attrs[0].val.programmaticStreamSerializationAllowed = 1;
    cfg.attrs = attrs;
    cfg.numAttrs = 1;
    cudaLaunchKernelEx(&cfg, conv_main, x, g, kernels, out);
}

// round 12
// speedup vs baseline: 1.2161x; 1.2161x over previous
#include <cuda_runtime.h>

#define BB      4096
#define DD      8192
#define KK      5
#define GS      40
#define CKLEN   17
#define CKPAD   20                      // padded row length (5 aligned float4s)
#define NTHR    256
#define TILE    2048                    // outputs per block
#define TILES_PER_ROW (DD / TILE)       // 4

#define CNTHR   256                     // compose block size
#define CBLK    (BB / CNTHR)            // 16 compose blocks

// Composed per-row 17-tap kernels, padded to 20 floats (327 KB, L2-resident)
__device__ float g_ck[BB * CKPAD];

// ---------------------------------------------------------------------------
// Kernel 1: compose each row's 17-tap kernel. 16 blocks x 256 threads,
// one row per thread. The redundant per-block max_it reduce uses int4 loads
// (4 per thread, MLP=4) so the whole kernel is ~1us.
// ---------------------------------------------------------------------------
__global__ void __launch_bounds__(CNTHR)
compose_kernel(const int* __restrict__ g, const float* __restrict__ kernels)
{
    __shared__ int s_red[CNTHR / 32];
    const int t = threadIdx.x;
    const int b = blockIdx.x * CNTHR + t;

    // --- max_it reduce: 4096 ints as 1024 int4s, 4 per thread ---
    const int4* g4 = reinterpret_cast<const int4*>(g);
    int m = 0;
    #pragma unroll
    for (int q = 0; q < 4; q++) {
        int4 v = __ldg(g4 + t + q * CNTHR);
        int a0 = v.x < 0 ? -v.x : v.x;
        int a1 = v.y < 0 ? -v.y : v.y;
        int a2 = v.z < 0 ? -v.z : v.z;
        int a3 = v.w < 0 ? -v.w : v.w;
        m = max(m, max(max(a0, a1), max(a2, a3)));
    }
    m /= GS;
    #pragma unroll
    for (int o = 16; o > 0; o >>= 1)
        m = max(m, __shfl_xor_sync(0xffffffffu, m, o));
    if ((t & 31) == 0) s_red[t >> 5] = m;
    __syncthreads();
    int max_it = s_red[0];
    #pragma unroll
    for (int w = 1; w < CNTHR / 32; w++) max_it = max(max_it, s_red[w]);

    // --- this thread's row ---
    const int gv  = g[b];                   // L2 hit (just streamed)
    const int sgn = (gv > 0) - (gv < 0);
    const int av  = gv < 0 ? -gv : gv;
    const int it  = av / GS;
    const int rem = av - it * GS;

    const int midx = sgn * 40 + 40;
    const int fidx = rem * sgn + 40;

    float idk[KK], maxk[KK], fink[KK];
    #pragma unroll
    for (int j = 0; j < KK; j++) {
        idk[j]  = __ldg(kernels + 40   * KK + j);
        maxk[j] = __ldg(kernels + midx * KK + j);
        fink[j] = __ldg(kernels + fidx * KK + j);
    }

    float c[CKLEN];
    #pragma unroll
    for (int p = 0; p < CKLEN; p++) c[p] = 0.f;
    c[8] = 1.f;

    #pragma unroll
    for (int stage = 0; stage < 4; stage++) {
        float kk[KK];
        bool skip = false;
        if (stage == 3) {
            #pragma unroll
            for (int j = 0; j < KK; j++) kk[j] = fink[j];
        } else if (stage < it) {
            #pragma unroll
            for (int j = 0; j < KK; j++) kk[j] = maxk[j];
        } else if (stage < max_it) {
            #pragma unroll
            for (int j = 0; j < KK; j++) kk[j] = idk[j];
        } else {
            skip = true;                    // true delta -> identity
        }
        if (!skip) {
            float nc[CKLEN];
            #pragma unroll
            for (int p = 0; p < CKLEN; p++) {
                float a = 0.f;
                #pragma unroll
                for (int j = 0; j < KK; j++) {
                    int q = p - j + 2;
                    if (q >= 0 && q < CKLEN) a = fmaf(kk[j], c[q], a);
                }
                nc[p] = a;
            }
            #pragma unroll
            for (int p = 0; p < CKLEN; p++) c[p] = nc[p];
        }
    }

    // padded write: 17 taps + 3 zeros, as 5 aligned float4s
    float4* dst = reinterpret_cast<float4*>(g_ck + b * CKPAD);
    dst[0] = make_float4(c[0],  c[1],  c[2],  c[3]);
    dst[1] = make_float4(c[4],  c[5],  c[6],  c[7]);
    dst[2] = make_float4(c[8],  c[9],  c[10], c[11]);
    dst[3] = make_float4(c[12], c[13], c[14], c[15]);
    dst[4] = make_float4(c[16], 0.f,   0.f,   0.f);
}

// ---------------------------------------------------------------------------
// Kernel 2 (UNCHANGED round-10 body, proven 45.5us): 17-tap circular
// correlation, lane-interleaved float4s. All 10 x-window loads issued
// before the PDL sync so they overlap compose_kernel.
// ---------------------------------------------------------------------------
__global__ void __launch_bounds__(NTHR)
conv_main(const float* __restrict__ x, float* __restrict__ out)
{
    const int bid  = blockIdx.x;
    const int b    = bid >> 2;              // TILES_PER_ROW = 4
    const int tile = bid & 3;
    const int lane = threadIdx.x & 31;
    const int warp = threadIdx.x >> 5;

    const float* __restrict__ xr = x + (size_t)b * DD;
    float* __restrict__ orow     = out + (size_t)b * DD;

    const int base4 = tile * (TILE / 4) + warp * 64 + lane;  // float4 index
    const int d0 = base4 * 4;
    const int d1 = d0 + 128;

    // ---- issue all 10 window loads (x has no dependency on compose) ----
    float w0[20], w1[20];
    #pragma unroll
    for (int q = 0; q < 5; q++) {
        const int idx = (d0 - 8 + 4 * q) & (DD - 1);
        float4 v = __ldg(reinterpret_cast<const float4*>(xr + idx));
        w0[4*q+0] = v.x; w0[4*q+1] = v.y; w0[4*q+2] = v.z; w0[4*q+3] = v.w;
    }
    #pragma unroll
    for (int q = 0; q < 5; q++) {
        const int idx = (d1 - 8 + 4 * q) & (DD - 1);
        float4 v = __ldg(reinterpret_cast<const float4*>(xr + idx));
        w1[4*q+0] = v.x; w1[4*q+1] = v.y; w1[4*q+2] = v.z; w1[4*q+3] = v.w;
    }

#if __CUDA_ARCH__ >= 900
    cudaGridDependencySynchronize();   // wait for compose_kernel
#endif

    // row taps: 5 vector loads (uniform across block, L2-resident)
    float k[CKLEN];
    {
        const float4* ckp = reinterpret_cast<const float4*>(g_ck + b * CKPAD);
        float4 k0 = __ldg(ckp + 0);
        float4 k1 = __ldg(ckp + 1);
        float4 k2 = __ldg(ckp + 2);
        float4 k3 = __ldg(ckp + 3);
        float4 k4 = __ldg(ckp + 4);
        k[0]=k0.x;  k[1]=k0.y;  k[2]=k0.z;  k[3]=k0.w;
        k[4]=k1.x;  k[5]=k1.y;  k[6]=k1.z;  k[7]=k1.w;
        k[8]=k2.x;  k[9]=k2.y;  k[10]=k2.z; k[11]=k2.w;
        k[12]=k3.x; k[13]=k3.y; k[14]=k3.z; k[15]=k3.w;
        k[16]=k4.x;
    }

    // ---- round 0 ----
    {
        float a0 = 0.f, a1 = 0.f, a2 = 0.f, a3 = 0.f;
        #pragma unroll
        for (int p = 0; p < CKLEN; p++) {
            a0 = fmaf(k[p], w0[p + 0], a0);
            a1 = fmaf(k[p], w0[p + 1], a1);
            a2 = fmaf(k[p], w0[p + 2], a2);
            a3 = fmaf(k[p], w0[p + 3], a3);
        }
        __stcs(reinterpret_cast<float4*>(orow + d0), make_float4(a0, a1, a2, a3));
    }

    // ---- round 1 ----
    {
        float a0 = 0.f, a1 = 0.f, a2 = 0.f, a3 = 0.f;
        #pragma unroll
        for (int p = 0; p < CKLEN; p++) {
            a0 = fmaf(k[p], w1[p + 0], a0);
            a1 = fmaf(k[p], w1[p + 1], a1);
            a2 = fmaf(k[p], w1[p + 2], a2);
            a3 = fmaf(k[p], w1[p + 3], a3);
        }
        __stcs(reinterpret_cast<float4*>(orow + d1), make_float4(a0, a1, a2, a3));
    }
}

// ---------------------------------------------------------------------------
// Launch: lean compose, then conv with programmatic dependent launch so
// conv's x-load prologue overlaps compose + launch latency.
// ---------------------------------------------------------------------------
extern "C" void kernel_launch(void* const* d_in, const int* in_sizes, int n_in,
                              void* d_out, int out_size)
{
    const float* x       = (const float*)d_in[0];   // [4096, 8192] f32
    const int*   g       = (const int*)  d_in[1];   // [4096] i32
    const float* kernels = (const float*)d_in[2];   // [81, 5] f32
    float*       out     = (float*)d_out;           // [4096, 1, 8192] f32

    compose_kernel<<<CBLK, CNTHR>>>(g, kernels);

    cudaLaunchConfig_t cfg = {};
    cfg.gridDim  = dim3(BB * TILES_PER_ROW, 1, 1);
    cfg.blockDim = dim3(NTHR, 1, 1);
    cfg.dynamicSmemBytes = 0;
    cfg.stream = 0;   // legacy default stream (the one the harness captures)
    cudaLaunchAttribute attrs[1];
    attrs[0].id = cudaLaunchAttributeProgrammaticStreamSerialization;
    attrs[0].val.programmaticStreamSerializationAllowed = 1;
    cfg.attrs = attrs;
    cfg.numAttrs = 1;
    cudaLaunchKernelEx(&cfg, conv_main, x, out);
}